// round 14
// baseline (speedup 1.0000x reference)
#include <cuda_runtime.h>
#include <math.h>
#include <stdint.h>

// ---------------------------------------------------------------------------
// Problem constants (deterministic from setup_inputs)
// ---------------------------------------------------------------------------
#define B_    2
#define S0_   1536
#define S1_   384
#define S2_   128
#define S_    2048
#define HID_  896
#define NH_   14
#define NKV_  2
#define HD_   64
#define INTER_ 4864
#define GQA_  7
#define EPS_  1e-6f

// Pre-rounded tf32 weight scratch layout (element offsets)
#define OFF_Q 0LL
#define OFF_K 2408448LL
#define OFF_V 2752512LL
#define OFF_O 3096576LL
#define OFF_G 5505024LL
#define OFF_U 18579456LL
#define OFF_D 31653888LL
#define WTF_TOTAL 44728320LL

// ---------------------------------------------------------------------------
// Scratch (static __device__ — no allocations allowed in kernel_launch)
// ---------------------------------------------------------------------------
__device__ float g_h  [(size_t)B_*S_*HID_];
__device__ float g_q  [(size_t)B_*S_*NH_*HD_];
__device__ float g_k  [(size_t)B_*S_*NKV_*HD_];
__device__ float g_v  [(size_t)B_*S_*NKV_*HD_];
__device__ float g_att[(size_t)B_*S_*NH_*HD_];
__device__ float g_res[(size_t)B_*S_*HID_];
__device__ float g_h2 [(size_t)B_*S_*HID_];
__device__ float g_ga [(size_t)B_*S_*INTER_];
__device__ float g_ua [(size_t)B_*S_*INTER_];
__device__ float g_wtf[(size_t)WTF_TOTAL];

// ---------------------------------------------------------------------------
// tf32 RNA rounding helper (returns rounded value as float bit pattern)
// ---------------------------------------------------------------------------
__device__ __forceinline__ float rna(float x) {
    uint32_t u;
    asm("cvt.rna.tf32.f32 %0, %1;" : "=r"(u) : "f"(x));
    return __uint_as_float(u);
}

// ---------------------------------------------------------------------------
// Weight prep: convert all GEMM weights to RNA-rounded tf32 bits, once.
// ---------------------------------------------------------------------------
__global__ void wprep_kernel(const float* __restrict__ qW, const float* __restrict__ kW,
                             const float* __restrict__ vW, const float* __restrict__ oW,
                             const float* __restrict__ gW, const float* __restrict__ uW,
                             const float* __restrict__ dW, float* __restrict__ out)
{
    long long i = (long long)blockIdx.x * blockDim.x + threadIdx.x;
    long long stride = (long long)gridDim.x * blockDim.x;
    for (; i < WTF_TOTAL; i += stride) {
        float v;
        if      (i < OFF_K) v = qW[i];
        else if (i < OFF_V) v = kW[i - OFF_K];
        else if (i < OFF_O) v = vW[i - OFF_V];
        else if (i < OFF_G) v = oW[i - OFF_O];
        else if (i < OFF_U) v = gW[i - OFF_G];
        else if (i < OFF_D) v = uW[i - OFF_U];
        else                v = dW[i - OFF_D];
        out[i] = rna(v);
    }
}

// ---------------------------------------------------------------------------
// RMSNorm 1: segmented inputs -> h (output pre-rounded to tf32 for GEMM A)
// ---------------------------------------------------------------------------
__global__ void rmsnorm1_kernel(const float* __restrict__ x0,
                                const float* __restrict__ x1,
                                const float* __restrict__ x2,
                                const float* __restrict__ w,
                                float* __restrict__ out)
{
    int t = blockIdx.x;
    int b = t / S_, s = t % S_;
    const float* xp; int seg;
    if (s < S0_)            { seg = 0; xp = x0 + ((size_t)b*S0_ + s)        * HID_; }
    else if (s < S0_ + S1_) { seg = 1; xp = x1 + ((size_t)b*S1_ + (s-S0_)) * HID_; }
    else                    { seg = 2; xp = x2 + ((size_t)b*S2_ + (s-S0_-S1_)) * HID_; }

    float ss = 0.f;
    for (int i = threadIdx.x; i < HID_; i += blockDim.x) { float v = xp[i]; ss += v*v; }
    __shared__ float red[8];
    for (int o = 16; o > 0; o >>= 1) ss += __shfl_down_sync(0xffffffffu, ss, o);
    if ((threadIdx.x & 31) == 0) red[threadIdx.x >> 5] = ss;
    __syncthreads();
    __shared__ float s_rstd;
    if (threadIdx.x == 0) {
        float tot = 0.f;
        #pragma unroll
        for (int i = 0; i < 8; i++) tot += red[i];
        s_rstd = rsqrtf(tot / (float)HID_ + EPS_);
    }
    __syncthreads();
    float rstd = s_rstd;
    const float* wp = w + (size_t)seg * HID_;
    float* op = out + (size_t)t * HID_;
    for (int i = threadIdx.x; i < HID_; i += blockDim.x)
        op[i] = rna(xp[i] * rstd * wp[i]);
}

// ---------------------------------------------------------------------------
// RMSNorm 2: contiguous input -> out (pre-rounded)
// ---------------------------------------------------------------------------
__global__ void rmsnorm2_kernel(const float* __restrict__ x,
                                const float* __restrict__ w,
                                float* __restrict__ out)
{
    int t = blockIdx.x;
    int s = t % S_;
    int seg = (s < S0_) ? 0 : ((s < S0_ + S1_) ? 1 : 2);
    const float* xp = x + (size_t)t * HID_;

    float ss = 0.f;
    for (int i = threadIdx.x; i < HID_; i += blockDim.x) { float v = xp[i]; ss += v*v; }
    __shared__ float red[8];
    for (int o = 16; o > 0; o >>= 1) ss += __shfl_down_sync(0xffffffffu, ss, o);
    if ((threadIdx.x & 31) == 0) red[threadIdx.x >> 5] = ss;
    __syncthreads();
    __shared__ float s_rstd;
    if (threadIdx.x == 0) {
        float tot = 0.f;
        #pragma unroll
        for (int i = 0; i < 8; i++) tot += red[i];
        s_rstd = rsqrtf(tot / (float)HID_ + EPS_);
    }
    __syncthreads();
    float rstd = s_rstd;
    const float* wp = w + (size_t)seg * HID_;
    float* op = out + (size_t)t * HID_;
    for (int i = threadIdx.x; i < HID_; i += blockDim.x)
        op[i] = rna(xp[i] * rstd * wp[i]);
}

// ---------------------------------------------------------------------------
// Pipelined TF32 GEMM mainloop (shared by gemm_tc and gemm_qkv).
// Inputs must be pre-rounded tf32 bit patterns (no cvt in hot loop).
// Block tile 128x128, BK=16, 3-stage cp.async, 256 thr, 8 warps 2x4.
// 61.4KB smem/block + launch_bounds(256,2) + carveout=100 -> 2 blocks/SM.
// ---------------------------------------------------------------------------
#define PBK     16
#define PSTR    20
#define PSTAGES 3
#define GEMM_SMEM_BYTES (PSTAGES * 2 * 128 * PSTR * 4)   // 61440

__device__ __forceinline__ void mma_tf32(float d[4], const uint32_t a[4], const uint32_t b[2]) {
    asm volatile(
        "mma.sync.aligned.m16n8k8.row.col.f32.tf32.tf32.f32 "
        "{%0,%1,%2,%3}, {%4,%5,%6,%7}, {%8,%9}, {%0,%1,%2,%3};"
        : "+f"(d[0]), "+f"(d[1]), "+f"(d[2]), "+f"(d[3])
        : "r"(a[0]), "r"(a[1]), "r"(a[2]), "r"(a[3]), "r"(b[0]), "r"(b[1]));
}

#define CP16(dst, src) \
    asm volatile("cp.async.cg.shared.global [%0], [%1], 16;" :: "r"(dst), "l"(src))

__device__ __forceinline__ void gemm_mainloop(
    const float* gA0, const float* gB0, int nk,
    uint32_t sA0, uint32_t sB0, const float* smbase,
    int wm, int wn, int gid, int l4, float acc[4][4][4])
{
    const uint32_t stageBytes = 128 * PSTR * 4;

    #pragma unroll
    for (int s = 0; s < PSTAGES - 1; s++) {
        long long off = (long long)s * PBK;
        CP16(sA0 + s * stageBytes,      gA0 + off);
        CP16(sA0 + s * stageBytes + 16, gA0 + off + 4);
        CP16(sB0 + s * stageBytes,      gB0 + off);
        CP16(sB0 + s * stageBytes + 16, gB0 + off + 4);
        asm volatile("cp.async.commit_group;");
    }

    for (int kt = 0; kt < nk; kt++) {
        asm volatile("cp.async.wait_group %0;" :: "n"(PSTAGES - 2));
        __syncthreads();

        int st = kt % PSTAGES;
        const uint32_t* Ast = (const uint32_t*)(smbase + (size_t)st * 128 * PSTR);
        const uint32_t* Bst = (const uint32_t*)(smbase + (size_t)PSTAGES * 128 * PSTR
                                                        + (size_t)st * 128 * PSTR);

        #pragma unroll
        for (int kk = 0; kk < PBK; kk += 8) {
            uint32_t af[4][4], bf[4][2];
            #pragma unroll
            for (int mt = 0; mt < 4; mt++) {
                int rb = wm + mt * 16;
                af[mt][0] = Ast[(rb + gid    ) * PSTR + kk + l4    ];
                af[mt][1] = Ast[(rb + gid + 8) * PSTR + kk + l4    ];
                af[mt][2] = Ast[(rb + gid    ) * PSTR + kk + l4 + 4];
                af[mt][3] = Ast[(rb + gid + 8) * PSTR + kk + l4 + 4];
            }
            #pragma unroll
            for (int nt = 0; nt < 4; nt++) {
                int cb = wn + nt * 8;
                bf[nt][0] = Bst[(cb + gid) * PSTR + kk + l4    ];
                bf[nt][1] = Bst[(cb + gid) * PSTR + kk + l4 + 4];
            }
            #pragma unroll
            for (int mt = 0; mt < 4; mt++)
                #pragma unroll
                for (int nt = 0; nt < 4; nt++)
                    mma_tf32(acc[mt][nt], af[mt], bf[nt]);
        }

        int kn = kt + PSTAGES - 1;
        if (kn < nk) {
            int sn = kn % PSTAGES;
            long long off = (long long)kn * PBK;
            CP16(sA0 + sn * stageBytes,      gA0 + off);
            CP16(sA0 + sn * stageBytes + 16, gA0 + off + 4);
            CP16(sB0 + sn * stageBytes,      gB0 + off);
            CP16(sB0 + sn * stageBytes + 16, gB0 + off + 4);
        }
        asm volatile("cp.async.commit_group;");
    }
}

// ---------------------------------------------------------------------------
// Generic GEMM: C = A @ Wseg^T (+epilogue). Weights pre-rounded (3,N,K).
// RES_MODE: 0 = none, 1 = segmented residual (x0/x1/x2), 2 = contiguous,
//           3 = swiglu: out = rna(silu(r0[idx]) * acc)   (r0 = gate buffer)
// ---------------------------------------------------------------------------
template<int RES_MODE>
__global__ void __launch_bounds__(256, 2)
gemm_tc(const float* __restrict__ A, long long Ab,
        const float* __restrict__ Wb,
        const float* __restrict__ r0, const float* __restrict__ r1,
        const float* __restrict__ r2, long long Rb,
        float* __restrict__ C, long long Cb,
        int N, int K)
{
    extern __shared__ float sm[];

    int bz = blockIdx.z;
    int m0 = blockIdx.y * 128;
    int n0 = blockIdx.x * 128;
    int seg = (m0 < S0_) ? 0 : (m0 < S0_ + S1_ ? 1 : 2);

    const float* Ap = A + (long long)bz * Ab;
    const float* W  = Wb + (size_t)seg * N * K;

    int tid  = threadIdx.x;
    int lane = tid & 31;
    int wid  = tid >> 5;
    int wm = (wid & 1) * 64;
    int wn = (wid >> 1) * 32;
    int gid = lane >> 2;
    int l4  = lane & 3;

    int lrow = tid >> 1;
    int lc   = (tid & 1) * 8;
    const float* gA0 = Ap + (long long)(m0 + lrow) * K + lc;
    const float* gB0 = W  + (long long)(n0 + lrow) * K + lc;

    uint32_t smem_u32;
    asm("{ .reg .u64 t; cvta.to.shared.u64 t, %1; cvt.u32.u64 %0, t; }"
        : "=r"(smem_u32) : "l"(sm));
    uint32_t sA0 = smem_u32 + (uint32_t)(lrow * PSTR + lc) * 4;
    uint32_t sB0 = sA0 + PSTAGES * 128 * PSTR * 4;

    float acc[4][4][4];
    #pragma unroll
    for (int mt = 0; mt < 4; mt++)
        #pragma unroll
        for (int nt = 0; nt < 4; nt++)
            #pragma unroll
            for (int j = 0; j < 4; j++) acc[mt][nt][j] = 0.f;

    gemm_mainloop(gA0, gB0, K / PBK, sA0, sB0, sm, wm, wn, gid, l4, acc);

    const float* rseg = nullptr;
    int segstart = 0, seglen = 0;
    if (RES_MODE == 1) {
        if (seg == 0)      { rseg = r0; segstart = 0;         seglen = S0_; }
        else if (seg == 1) { rseg = r1; segstart = S0_;       seglen = S1_; }
        else               { rseg = r2; segstart = S0_ + S1_; seglen = S2_; }
    }

    float* Cp = C + (long long)bz * Cb;

    #pragma unroll
    for (int mt = 0; mt < 4; mt++) {
        #pragma unroll
        for (int nt = 0; nt < 4; nt++) {
            int mrow = m0 + wm + mt * 16 + gid;
            int col  = n0 + wn + nt * 8 + 2 * l4;
            float2 v0 = make_float2(acc[mt][nt][0], acc[mt][nt][1]);
            float2 v1 = make_float2(acc[mt][nt][2], acc[mt][nt][3]);
            if (RES_MODE == 1) {
                long long base0 = ((long long)bz * seglen + (mrow - segstart)) * N + col;
                long long base1 = ((long long)bz * seglen + (mrow + 8 - segstart)) * N + col;
                float2 q0 = *(const float2*)&rseg[base0];
                float2 q1 = *(const float2*)&rseg[base1];
                v0.x += q0.x; v0.y += q0.y;
                v1.x += q1.x; v1.y += q1.y;
            } else if (RES_MODE == 2) {
                const float* Rp = r0 + (long long)bz * Rb;
                float2 q0 = *(const float2*)&Rp[(long long)mrow * N + col];
                float2 q1 = *(const float2*)&Rp[(long long)(mrow + 8) * N + col];
                v0.x += q0.x; v0.y += q0.y;
                v1.x += q1.x; v1.y += q1.y;
            } else if (RES_MODE == 3) {
                const float* Gp = r0 + (long long)bz * Rb;
                float2 g0 = *(const float2*)&Gp[(long long)mrow * N + col];
                float2 g1 = *(const float2*)&Gp[(long long)(mrow + 8) * N + col];
                v0.x = rna((g0.x / (1.f + expf(-g0.x))) * v0.x);
                v0.y = rna((g0.y / (1.f + expf(-g0.y))) * v0.y);
                v1.x = rna((g1.x / (1.f + expf(-g1.x))) * v1.x);
                v1.y = rna((g1.y / (1.f + expf(-g1.y))) * v1.y);
            }
            *(float2*)&Cp[(long long)mrow * N + col]       = v0;
            *(float2*)&Cp[(long long)(mrow + 8) * N + col] = v1;
        }
    }
}

// ---------------------------------------------------------------------------
// Fused QKV GEMM: grid.x = 9 n-tiles (0-6: q cols, 7: k, 8: v). K = HID.
// ---------------------------------------------------------------------------
__global__ void __launch_bounds__(256, 2)
gemm_qkv(const float* __restrict__ A,
         const float* __restrict__ Wtf,
         const float* __restrict__ qb, const float* __restrict__ kb,
         const float* __restrict__ vb,
         float* __restrict__ qo, float* __restrict__ ko, float* __restrict__ vo)
{
    extern __shared__ float sm[];

    int bz = blockIdx.z;
    int m0 = blockIdx.y * 128;
    int tx = blockIdx.x;
    int seg = (m0 < S0_) ? 0 : (m0 < S0_ + S1_ ? 1 : 2);

    const int K = HID_;
    const float* Ap = A + (long long)bz * S_ * HID_;

    const float* W; const float* bp; float* Out; int Nout; int cb0;
    if (tx < 7) {
        W = Wtf + OFF_Q + (size_t)seg * 896 * 896 + (size_t)(tx * 128) * 896;
        bp = qb + (size_t)seg * 896 + tx * 128;
        Out = qo + (long long)bz * S_ * 896; Nout = 896; cb0 = tx * 128;
    } else if (tx == 7) {
        W = Wtf + OFF_K + (size_t)seg * 128 * 896;
        bp = kb + (size_t)seg * 128;
        Out = ko + (long long)bz * S_ * 128; Nout = 128; cb0 = 0;
    } else {
        W = Wtf + OFF_V + (size_t)seg * 128 * 896;
        bp = vb + (size_t)seg * 128;
        Out = vo + (long long)bz * S_ * 128; Nout = 128; cb0 = 0;
    }

    int tid  = threadIdx.x;
    int lane = tid & 31;
    int wid  = tid >> 5;
    int wm = (wid & 1) * 64;
    int wn = (wid >> 1) * 32;
    int gid = lane >> 2;
    int l4  = lane & 3;

    int lrow = tid >> 1;
    int lc   = (tid & 1) * 8;
    const float* gA0 = Ap + (long long)(m0 + lrow) * K + lc;
    const float* gB0 = W  + (long long)lrow * K + lc;

    uint32_t smem_u32;
    asm("{ .reg .u64 t; cvta.to.shared.u64 t, %1; cvt.u32.u64 %0, t; }"
        : "=r"(smem_u32) : "l"(sm));
    uint32_t sA0 = smem_u32 + (uint32_t)(lrow * PSTR + lc) * 4;
    uint32_t sB0 = sA0 + PSTAGES * 128 * PSTR * 4;

    float acc[4][4][4];
    #pragma unroll
    for (int mt = 0; mt < 4; mt++)
        #pragma unroll
        for (int nt = 0; nt < 4; nt++)
            #pragma unroll
            for (int j = 0; j < 4; j++) acc[mt][nt][j] = 0.f;

    gemm_mainloop(gA0, gB0, K / PBK, sA0, sB0, sm, wm, wn, gid, l4, acc);

    #pragma unroll
    for (int mt = 0; mt < 4; mt++) {
        #pragma unroll
        for (int nt = 0; nt < 4; nt++) {
            int mrow = m0 + wm + mt * 16 + gid;
            int cl   = wn + nt * 8 + 2 * l4;     // 0..127 within tile
            float b0 = bp[cl], b1 = bp[cl + 1];
            float2 v0 = make_float2(acc[mt][nt][0] + b0, acc[mt][nt][1] + b1);
            float2 v1 = make_float2(acc[mt][nt][2] + b0, acc[mt][nt][3] + b1);
            *(float2*)&Out[(long long)mrow * Nout + cb0 + cl]       = v0;
            *(float2*)&Out[(long long)(mrow + 8) * Nout + cb0 + cl] = v1;
        }
    }
}

// ---------------------------------------------------------------------------
// RoPE (in place on q and k). position id == s, theta = 1e6.
// ---------------------------------------------------------------------------
__global__ void rope_kernel(float* __restrict__ q, float* __restrict__ k)
{
    __shared__ float cs[32], sn[32];
    int t = blockIdx.x;
    int s = t % S_;
    if (threadIdx.x < 32) {
        int d = threadIdx.x;
        float inv = exp2f(-0.622664268228770f * (float)d);  // 1e6^(-d/32)
        float f = (float)s * inv;
        cs[d] = cosf(f);
        sn[d] = sinf(f);
    }
    __syncthreads();
    const int NQITEMS = NH_ * 32;
    const int NTOT = (NH_ + NKV_) * 32;
    for (int it = threadIdx.x; it < NTOT; it += blockDim.x) {
        float* base; int d;
        if (it < NQITEMS) { base = q + (size_t)t*NH_*HD_  + (it >> 5) * HD_; d = it & 31; }
        else { int j = it - NQITEMS; base = k + (size_t)t*NKV_*HD_ + (j >> 5) * HD_; d = j & 31; }
        float c = cs[d], sv = sn[d];
        float x1 = base[d], x2 = base[d + 32];
        base[d]      = x1 * c - x2 * sv;
        base[d + 32] = x2 * c + x1 * sv;
    }
}

// ---------------------------------------------------------------------------
// Attention: flash-style online softmax, split-HD, 64-row K/V tiles.
// 128 threads = 64 q rows x 2 halves. Output pre-rounded (feeds O-proj GEMM).
// Inner loops use explicit float4 smem loads: one LDS.128 feeds 4 FMAs
// (rows are 68 floats = 272B = 17*16B -> every [row][4k] is 16B-aligned).
// Mask: allowed(q,k) = (k<S0) || (k<=q).
// ---------------------------------------------------------------------------
__global__ void __launch_bounds__(128)
attn_kernel(const float* __restrict__ q, const float* __restrict__ k,
            const float* __restrict__ v, float* __restrict__ o)
{
    __shared__ float ks[64][68];
    __shared__ float vs[64][68];

    int qt = blockIdx.x, h = blockIdx.y, b = blockIdx.z;
    int kvh = h / GQA_;
    int tid = threadIdx.x;
    int lane = tid & 31, wid = tid >> 5;
    int row  = wid * 16 + (lane >> 1);
    int half = lane & 1;
    int d0   = half * 32;
    int qrow = qt * 64 + row;
    long long tq = (long long)b * S_ + qrow;

    float qreg[32];
    const float* qp = q + tq * (NH_*HD_) + h * HD_ + d0;
    #pragma unroll
    for (int d = 0; d < 32; d++) qreg[d] = qp[d] * 0.125f;

    float oacc[32];
    #pragma unroll
    for (int d = 0; d < 32; d++) oacc[d] = 0.f;
    float m = -1e30f, l = 0.f;

    int qend = qt * 64 + 63;
    int kmax = (qend < S0_) ? S0_ : (qend + 1);   // multiple of 64

    for (int k0 = 0; k0 < kmax; k0 += 64) {
        #pragma unroll
        for (int j = 0; j < 8; j++) {
            int idx = tid + 128 * j;
            int r = idx >> 4;
            int c = (idx & 15) * 4;
            const float* kp = k + ((long long)b*S_ + k0 + r) * (NKV_*HD_) + kvh*HD_ + c;
            const float* vp = v + ((long long)b*S_ + k0 + r) * (NKV_*HD_) + kvh*HD_ + c;
            *(float4*)&ks[r][c] = *(const float4*)kp;
            *(float4*)&vs[r][c] = *(const float4*)vp;
        }
        __syncthreads();

        #pragma unroll
        for (int sub = 0; sub < 2; sub++) {
            int kb0 = sub * 32;
            float sc[32];
            float tmax = -1e30f;
            #pragma unroll
            for (int kk = 0; kk < 32; kk++) {
                float s0 = 0.f, s1 = 0.f, s2 = 0.f, s3 = 0.f;
                #pragma unroll
                for (int d = 0; d < 32; d += 4) {
                    float4 kv = *(const float4*)&ks[kb0+kk][d0+d];
                    s0 += qreg[d+0] * kv.x;
                    s1 += qreg[d+1] * kv.y;
                    s2 += qreg[d+2] * kv.z;
                    s3 += qreg[d+3] * kv.w;
                }
                float part = (s0 + s1) + (s2 + s3);
                float full = part + __shfl_xor_sync(0xffffffffu, part, 1);
                int kidx = k0 + kb0 + kk;
                if (kidx > qrow && kidx >= S0_) full = -1e30f;
                sc[kk] = full;
                tmax = fmaxf(tmax, full);
            }

            float mnew = fmaxf(m, tmax);
            float corr = __expf(m - mnew);
            l *= corr;
            #pragma unroll
            for (int d = 0; d < 32; d++) oacc[d] *= corr;
            #pragma unroll
            for (int kk = 0; kk < 32; kk++) {
                float p = __expf(sc[kk] - mnew);
                l += p;
                #pragma unroll
                for (int d = 0; d < 32; d += 4) {
                    float4 vv = *(const float4*)&vs[kb0+kk][d0+d];
                    oacc[d+0] += p * vv.x;
                    oacc[d+1] += p * vv.y;
                    oacc[d+2] += p * vv.z;
                    oacc[d+3] += p * vv.w;
                }
            }
            m = mnew;
        }
        __syncthreads();
    }

    float inv_l = 1.f / l;
    float* op = o + tq * (NH_*HD_) + h * HD_ + d0;
    #pragma unroll
    for (int d = 0; d < 32; d++) op[d] = rna(oacc[d] * inv_l);
}

// ---------------------------------------------------------------------------
// Host launcher
// ---------------------------------------------------------------------------
extern "C" void kernel_launch(void* const* d_in, const int* in_sizes, int n_in,
                              void* d_out, int out_size)
{
    const float* x0 = (const float*)d_in[0];
    const float* x1 = (const float*)d_in[1];
    const float* x2 = (const float*)d_in[2];
    const float* qW = (const float*)d_in[3];
    const float* qb = (const float*)d_in[4];
    const float* kW = (const float*)d_in[5];
    const float* kb = (const float*)d_in[6];
    const float* vW = (const float*)d_in[7];
    const float* vb = (const float*)d_in[8];
    const float* oW = (const float*)d_in[9];
    const float* ln1 = (const float*)d_in[10];
    const float* ln2 = (const float*)d_in[11];
    const float* gW = (const float*)d_in[12];
    const float* uW = (const float*)d_in[13];
    const float* dW = (const float*)d_in[14];
    float* out = (float*)d_out;

    float *h, *q, *k, *v, *att, *res, *h2, *ga, *ua, *wtf;
    cudaGetSymbolAddress((void**)&h,   g_h);
    cudaGetSymbolAddress((void**)&q,   g_q);
    cudaGetSymbolAddress((void**)&k,   g_k);
    cudaGetSymbolAddress((void**)&v,   g_v);
    cudaGetSymbolAddress((void**)&att, g_att);
    cudaGetSymbolAddress((void**)&res, g_res);
    cudaGetSymbolAddress((void**)&h2,  g_h2);
    cudaGetSymbolAddress((void**)&ga,  g_ga);
    cudaGetSymbolAddress((void**)&ua,  g_ua);
    cudaGetSymbolAddress((void**)&wtf, g_wtf);

    cudaFuncSetAttribute(gemm_tc<0>, cudaFuncAttributeMaxDynamicSharedMemorySize, GEMM_SMEM_BYTES);
    cudaFuncSetAttribute(gemm_tc<1>, cudaFuncAttributeMaxDynamicSharedMemorySize, GEMM_SMEM_BYTES);
    cudaFuncSetAttribute(gemm_tc<2>, cudaFuncAttributeMaxDynamicSharedMemorySize, GEMM_SMEM_BYTES);
    cudaFuncSetAttribute(gemm_tc<3>, cudaFuncAttributeMaxDynamicSharedMemorySize, GEMM_SMEM_BYTES);
    cudaFuncSetAttribute(gemm_qkv,   cudaFuncAttributeMaxDynamicSharedMemorySize, GEMM_SMEM_BYTES);
    // maximize smem carveout so two 61.4KB blocks fit per SM
    cudaFuncSetAttribute(gemm_tc<0>, cudaFuncAttributePreferredSharedMemoryCarveout, 100);
    cudaFuncSetAttribute(gemm_tc<1>, cudaFuncAttributePreferredSharedMemoryCarveout, 100);
    cudaFuncSetAttribute(gemm_tc<2>, cudaFuncAttributePreferredSharedMemoryCarveout, 100);
    cudaFuncSetAttribute(gemm_tc<3>, cudaFuncAttributePreferredSharedMemoryCarveout, 100);
    cudaFuncSetAttribute(gemm_qkv,   cudaFuncAttributePreferredSharedMemoryCarveout, 100);

    const int MT = S_ / 128;   // 16 m-tiles

    // 0. Weight prep: RNA-round all weights into tf32-bit scratch
    wprep_kernel<<<2048, 256>>>(qW, kW, vW, oW, gW, uW, dW, wtf);

    // 1. RMSNorm(ln1) -> h (pre-rounded)
    rmsnorm1_kernel<<<B_ * S_, 256>>>(x0, x1, x2, ln1, h);

    // 2. Fused QKV projection (one launch)
    gemm_qkv<<<dim3(9, MT, B_), 256, GEMM_SMEM_BYTES>>>(h, wtf, qb, kb, vb, q, k, v);

    // 3. RoPE (in place)
    rope_kernel<<<B_ * S_, 256>>>(q, k);

    // 4. Attention (output pre-rounded)
    attn_kernel<<<dim3(S_ / 64, NH_, B_), 128>>>(q, k, v, att);

    // 5. O projection + segmented residual -> res
    gemm_tc<1><<<dim3(HID_/128, MT, B_), 256, GEMM_SMEM_BYTES>>>(
        att, (long long)S_*HID_, wtf + OFF_O, x0, x1, x2, 0,
        res, (long long)S_*HID_, HID_, HID_);

    // 6. RMSNorm(ln2) -> h2 (pre-rounded)
    rmsnorm2_kernel<<<B_ * S_, 256>>>(res, ln2, h2);

    // 7. MLP: gate GEMM -> ga (raw), then up GEMM with fused swiglu -> ua
    gemm_tc<0><<<dim3(INTER_/128, MT, B_), 256, GEMM_SMEM_BYTES>>>(
        h2, (long long)S_*HID_, wtf + OFF_G, nullptr, nullptr, nullptr, 0,
        ga, (long long)S_*INTER_, INTER_, HID_);
    gemm_tc<3><<<dim3(INTER_/128, MT, B_), 256, GEMM_SMEM_BYTES>>>(
        h2, (long long)S_*HID_, wtf + OFF_U, ga, nullptr, nullptr, (long long)S_*INTER_,
        ua, (long long)S_*INTER_, INTER_, HID_);

    // 8. Down projection + contiguous residual -> out
    gemm_tc<2><<<dim3(HID_/128, MT, B_), 256, GEMM_SMEM_BYTES>>>(
        ua, (long long)S_*INTER_, wtf + OFF_D, res, nullptr, nullptr, (long long)S_*HID_,
        out, (long long)S_*HID_, HID_, INTER_);
}

// round 17
// speedup vs baseline: 1.8620x; 1.8620x over previous
#include <cuda_runtime.h>
#include <math.h>
#include <stdint.h>

// ---------------------------------------------------------------------------
// Problem constants (deterministic from setup_inputs)
// ---------------------------------------------------------------------------
#define B_    2
#define S0_   1536
#define S1_   384
#define S2_   128
#define S_    2048
#define HID_  896
#define NH_   14
#define NKV_  2
#define HD_   64
#define INTER_ 4864
#define GQA_  7
#define EPS_  1e-6f

// Pre-rounded tf32 weight scratch layout (element offsets)
#define OFF_Q 0LL
#define OFF_K 2408448LL
#define OFF_V 2752512LL
#define OFF_O 3096576LL
#define OFF_G 5505024LL
#define OFF_U 18579456LL
#define OFF_D 31653888LL
#define WTF_TOTAL 44728320LL

// ---------------------------------------------------------------------------
// Scratch (static __device__ — no allocations allowed in kernel_launch)
// ---------------------------------------------------------------------------
__device__ float g_h  [(size_t)B_*S_*HID_];
__device__ float g_q  [(size_t)B_*S_*NH_*HD_];
__device__ float g_k  [(size_t)B_*S_*NKV_*HD_];
__device__ float g_v  [(size_t)B_*S_*NKV_*HD_];
__device__ float g_att[(size_t)B_*S_*NH_*HD_];
__device__ float g_res[(size_t)B_*S_*HID_];
__device__ float g_h2 [(size_t)B_*S_*HID_];
__device__ float g_ga [(size_t)B_*S_*INTER_];
__device__ float g_ua [(size_t)B_*S_*INTER_];
__device__ float g_wtf[(size_t)WTF_TOTAL];

// ---------------------------------------------------------------------------
// tf32 RNA rounding helper
// ---------------------------------------------------------------------------
__device__ __forceinline__ float rna(float x) {
    uint32_t u;
    asm("cvt.rna.tf32.f32 %0, %1;" : "=r"(u) : "f"(x));
    return __uint_as_float(u);
}

// ---------------------------------------------------------------------------
// Weight prep: convert all GEMM weights to RNA-rounded tf32 bits, once.
// ---------------------------------------------------------------------------
__global__ void wprep_kernel(const float* __restrict__ qW, const float* __restrict__ kW,
                             const float* __restrict__ vW, const float* __restrict__ oW,
                             const float* __restrict__ gW, const float* __restrict__ uW,
                             const float* __restrict__ dW, float* __restrict__ out)
{
    long long i = (long long)blockIdx.x * blockDim.x + threadIdx.x;
    long long stride = (long long)gridDim.x * blockDim.x;
    for (; i < WTF_TOTAL; i += stride) {
        float v;
        if      (i < OFF_K) v = qW[i];
        else if (i < OFF_V) v = kW[i - OFF_K];
        else if (i < OFF_O) v = vW[i - OFF_V];
        else if (i < OFF_G) v = oW[i - OFF_O];
        else if (i < OFF_U) v = gW[i - OFF_G];
        else if (i < OFF_D) v = uW[i - OFF_U];
        else                v = dW[i - OFF_D];
        out[i] = rna(v);
    }
}

// ---------------------------------------------------------------------------
// RMSNorm 1: segmented inputs -> h (pre-rounded)
// ---------------------------------------------------------------------------
__global__ void rmsnorm1_kernel(const float* __restrict__ x0,
                                const float* __restrict__ x1,
                                const float* __restrict__ x2,
                                const float* __restrict__ w,
                                float* __restrict__ out)
{
    int t = blockIdx.x;
    int b = t / S_, s = t % S_;
    const float* xp; int seg;
    if (s < S0_)            { seg = 0; xp = x0 + ((size_t)b*S0_ + s)        * HID_; }
    else if (s < S0_ + S1_) { seg = 1; xp = x1 + ((size_t)b*S1_ + (s-S0_)) * HID_; }
    else                    { seg = 2; xp = x2 + ((size_t)b*S2_ + (s-S0_-S1_)) * HID_; }

    float ss = 0.f;
    for (int i = threadIdx.x; i < HID_; i += blockDim.x) { float v = xp[i]; ss += v*v; }
    __shared__ float red[8];
    for (int o = 16; o > 0; o >>= 1) ss += __shfl_down_sync(0xffffffffu, ss, o);
    if ((threadIdx.x & 31) == 0) red[threadIdx.x >> 5] = ss;
    __syncthreads();
    __shared__ float s_rstd;
    if (threadIdx.x == 0) {
        float tot = 0.f;
        #pragma unroll
        for (int i = 0; i < 8; i++) tot += red[i];
        s_rstd = rsqrtf(tot / (float)HID_ + EPS_);
    }
    __syncthreads();
    float rstd = s_rstd;
    const float* wp = w + (size_t)seg * HID_;
    float* op = out + (size_t)t * HID_;
    for (int i = threadIdx.x; i < HID_; i += blockDim.x)
        op[i] = rna(xp[i] * rstd * wp[i]);
}

// ---------------------------------------------------------------------------
// RMSNorm 2: contiguous input -> out (pre-rounded)
// ---------------------------------------------------------------------------
__global__ void rmsnorm2_kernel(const float* __restrict__ x,
                                const float* __restrict__ w,
                                float* __restrict__ out)
{
    int t = blockIdx.x;
    int s = t % S_;
    int seg = (s < S0_) ? 0 : ((s < S0_ + S1_) ? 1 : 2);
    const float* xp = x + (size_t)t * HID_;

    float ss = 0.f;
    for (int i = threadIdx.x; i < HID_; i += blockDim.x) { float v = xp[i]; ss += v*v; }
    __shared__ float red[8];
    for (int o = 16; o > 0; o >>= 1) ss += __shfl_down_sync(0xffffffffu, ss, o);
    if ((threadIdx.x & 31) == 0) red[threadIdx.x >> 5] = ss;
    __syncthreads();
    __shared__ float s_rstd;
    if (threadIdx.x == 0) {
        float tot = 0.f;
        #pragma unroll
        for (int i = 0; i < 8; i++) tot += red[i];
        s_rstd = rsqrtf(tot / (float)HID_ + EPS_);
    }
    __syncthreads();
    float rstd = s_rstd;
    const float* wp = w + (size_t)seg * HID_;
    float* op = out + (size_t)t * HID_;
    for (int i = threadIdx.x; i < HID_; i += blockDim.x)
        op[i] = rna(xp[i] * rstd * wp[i]);
}

// ---------------------------------------------------------------------------
// Pipelined TF32 GEMM mainloop (unchanged from 2970us baseline)
// ---------------------------------------------------------------------------
#define PBK     16
#define PSTR    20
#define PSTAGES 3
#define GEMM_SMEM_BYTES (PSTAGES * 2 * 128 * PSTR * 4)   // 61440

__device__ __forceinline__ void mma_tf32(float d[4], const uint32_t a[4], const uint32_t b[2]) {
    asm volatile(
        "mma.sync.aligned.m16n8k8.row.col.f32.tf32.tf32.f32 "
        "{%0,%1,%2,%3}, {%4,%5,%6,%7}, {%8,%9}, {%0,%1,%2,%3};"
        : "+f"(d[0]), "+f"(d[1]), "+f"(d[2]), "+f"(d[3])
        : "r"(a[0]), "r"(a[1]), "r"(a[2]), "r"(a[3]), "r"(b[0]), "r"(b[1]));
}

#define CP16(dst, src) \
    asm volatile("cp.async.cg.shared.global [%0], [%1], 16;" :: "r"(dst), "l"(src))

__device__ __forceinline__ void gemm_mainloop(
    const float* gA0, const float* gB0, int nk,
    uint32_t sA0, uint32_t sB0, const float* smbase,
    int wm, int wn, int gid, int l4, float acc[4][4][4])
{
    const uint32_t stageBytes = 128 * PSTR * 4;

    #pragma unroll
    for (int s = 0; s < PSTAGES - 1; s++) {
        long long off = (long long)s * PBK;
        CP16(sA0 + s * stageBytes,      gA0 + off);
        CP16(sA0 + s * stageBytes + 16, gA0 + off + 4);
        CP16(sB0 + s * stageBytes,      gB0 + off);
        CP16(sB0 + s * stageBytes + 16, gB0 + off + 4);
        asm volatile("cp.async.commit_group;");
    }

    for (int kt = 0; kt < nk; kt++) {
        asm volatile("cp.async.wait_group %0;" :: "n"(PSTAGES - 2));
        __syncthreads();

        int st = kt % PSTAGES;
        const uint32_t* Ast = (const uint32_t*)(smbase + (size_t)st * 128 * PSTR);
        const uint32_t* Bst = (const uint32_t*)(smbase + (size_t)PSTAGES * 128 * PSTR
                                                        + (size_t)st * 128 * PSTR);

        #pragma unroll
        for (int kk = 0; kk < PBK; kk += 8) {
            uint32_t af[4][4], bf[4][2];
            #pragma unroll
            for (int mt = 0; mt < 4; mt++) {
                int rb = wm + mt * 16;
                af[mt][0] = Ast[(rb + gid    ) * PSTR + kk + l4    ];
                af[mt][1] = Ast[(rb + gid + 8) * PSTR + kk + l4    ];
                af[mt][2] = Ast[(rb + gid    ) * PSTR + kk + l4 + 4];
                af[mt][3] = Ast[(rb + gid + 8) * PSTR + kk + l4 + 4];
            }
            #pragma unroll
            for (int nt = 0; nt < 4; nt++) {
                int cb = wn + nt * 8;
                bf[nt][0] = Bst[(cb + gid) * PSTR + kk + l4    ];
                bf[nt][1] = Bst[(cb + gid) * PSTR + kk + l4 + 4];
            }
            #pragma unroll
            for (int mt = 0; mt < 4; mt++)
                #pragma unroll
                for (int nt = 0; nt < 4; nt++)
                    mma_tf32(acc[mt][nt], af[mt], bf[nt]);
        }

        int kn = kt + PSTAGES - 1;
        if (kn < nk) {
            int sn = kn % PSTAGES;
            long long off = (long long)kn * PBK;
            CP16(sA0 + sn * stageBytes,      gA0 + off);
            CP16(sA0 + sn * stageBytes + 16, gA0 + off + 4);
            CP16(sB0 + sn * stageBytes,      gB0 + off);
            CP16(sB0 + sn * stageBytes + 16, gB0 + off + 4);
        }
        asm volatile("cp.async.commit_group;");
    }
}

// ---------------------------------------------------------------------------
// Generic GEMM (unchanged). RES_MODE: 0 none, 1 segmented, 2 contiguous,
// 3 swiglu: out = rna(silu(gate)*acc)
// ---------------------------------------------------------------------------
template<int RES_MODE>
__global__ void __launch_bounds__(256, 2)
gemm_tc(const float* __restrict__ A, long long Ab,
        const float* __restrict__ Wb,
        const float* __restrict__ r0, const float* __restrict__ r1,
        const float* __restrict__ r2, long long Rb,
        float* __restrict__ C, long long Cb,
        int N, int K)
{
    extern __shared__ float sm[];

    int bz = blockIdx.z;
    int m0 = blockIdx.y * 128;
    int n0 = blockIdx.x * 128;
    int seg = (m0 < S0_) ? 0 : (m0 < S0_ + S1_ ? 1 : 2);

    const float* Ap = A + (long long)bz * Ab;
    const float* W  = Wb + (size_t)seg * N * K;

    int tid  = threadIdx.x;
    int lane = tid & 31;
    int wid  = tid >> 5;
    int wm = (wid & 1) * 64;
    int wn = (wid >> 1) * 32;
    int gid = lane >> 2;
    int l4  = lane & 3;

    int lrow = tid >> 1;
    int lc   = (tid & 1) * 8;
    const float* gA0 = Ap + (long long)(m0 + lrow) * K + lc;
    const float* gB0 = W  + (long long)(n0 + lrow) * K + lc;

    uint32_t smem_u32;
    asm("{ .reg .u64 t; cvta.to.shared.u64 t, %1; cvt.u32.u64 %0, t; }"
        : "=r"(smem_u32) : "l"(sm));
    uint32_t sA0 = smem_u32 + (uint32_t)(lrow * PSTR + lc) * 4;
    uint32_t sB0 = sA0 + PSTAGES * 128 * PSTR * 4;

    float acc[4][4][4];
    #pragma unroll
    for (int mt = 0; mt < 4; mt++)
        #pragma unroll
        for (int nt = 0; nt < 4; nt++)
            #pragma unroll
            for (int j = 0; j < 4; j++) acc[mt][nt][j] = 0.f;

    gemm_mainloop(gA0, gB0, K / PBK, sA0, sB0, sm, wm, wn, gid, l4, acc);

    const float* rseg = nullptr;
    int segstart = 0, seglen = 0;
    if (RES_MODE == 1) {
        if (seg == 0)      { rseg = r0; segstart = 0;         seglen = S0_; }
        else if (seg == 1) { rseg = r1; segstart = S0_;       seglen = S1_; }
        else               { rseg = r2; segstart = S0_ + S1_; seglen = S2_; }
    }

    float* Cp = C + (long long)bz * Cb;

    #pragma unroll
    for (int mt = 0; mt < 4; mt++) {
        #pragma unroll
        for (int nt = 0; nt < 4; nt++) {
            int mrow = m0 + wm + mt * 16 + gid;
            int col  = n0 + wn + nt * 8 + 2 * l4;
            float2 v0 = make_float2(acc[mt][nt][0], acc[mt][nt][1]);
            float2 v1 = make_float2(acc[mt][nt][2], acc[mt][nt][3]);
            if (RES_MODE == 1) {
                long long base0 = ((long long)bz * seglen + (mrow - segstart)) * N + col;
                long long base1 = ((long long)bz * seglen + (mrow + 8 - segstart)) * N + col;
                float2 q0 = *(const float2*)&rseg[base0];
                float2 q1 = *(const float2*)&rseg[base1];
                v0.x += q0.x; v0.y += q0.y;
                v1.x += q1.x; v1.y += q1.y;
            } else if (RES_MODE == 2) {
                const float* Rp = r0 + (long long)bz * Rb;
                float2 q0 = *(const float2*)&Rp[(long long)mrow * N + col];
                float2 q1 = *(const float2*)&Rp[(long long)(mrow + 8) * N + col];
                v0.x += q0.x; v0.y += q0.y;
                v1.x += q1.x; v1.y += q1.y;
            } else if (RES_MODE == 3) {
                const float* Gp = r0 + (long long)bz * Rb;
                float2 g0 = *(const float2*)&Gp[(long long)mrow * N + col];
                float2 g1 = *(const float2*)&Gp[(long long)(mrow + 8) * N + col];
                v0.x = rna((g0.x / (1.f + expf(-g0.x))) * v0.x);
                v0.y = rna((g0.y / (1.f + expf(-g0.y))) * v0.y);
                v1.x = rna((g1.x / (1.f + expf(-g1.x))) * v1.x);
                v1.y = rna((g1.y / (1.f + expf(-g1.y))) * v1.y);
            }
            *(float2*)&Cp[(long long)mrow * N + col]       = v0;
            *(float2*)&Cp[(long long)(mrow + 8) * N + col] = v1;
        }
    }
}

// ---------------------------------------------------------------------------
// Fused QKV GEMM (unchanged): grid.x = 9 n-tiles (0-6 q, 7 k, 8 v)
// ---------------------------------------------------------------------------
__global__ void __launch_bounds__(256, 2)
gemm_qkv(const float* __restrict__ A,
         const float* __restrict__ Wtf,
         const float* __restrict__ qb, const float* __restrict__ kb,
         const float* __restrict__ vb,
         float* __restrict__ qo, float* __restrict__ ko, float* __restrict__ vo)
{
    extern __shared__ float sm[];

    int bz = blockIdx.z;
    int m0 = blockIdx.y * 128;
    int tx = blockIdx.x;
    int seg = (m0 < S0_) ? 0 : (m0 < S0_ + S1_ ? 1 : 2);

    const int K = HID_;
    const float* Ap = A + (long long)bz * S_ * HID_;

    const float* W; const float* bp; float* Out; int Nout; int cb0;
    if (tx < 7) {
        W = Wtf + OFF_Q + (size_t)seg * 896 * 896 + (size_t)(tx * 128) * 896;
        bp = qb + (size_t)seg * 896 + tx * 128;
        Out = qo + (long long)bz * S_ * 896; Nout = 896; cb0 = tx * 128;
    } else if (tx == 7) {
        W = Wtf + OFF_K + (size_t)seg * 128 * 896;
        bp = kb + (size_t)seg * 128;
        Out = ko + (long long)bz * S_ * 128; Nout = 128; cb0 = 0;
    } else {
        W = Wtf + OFF_V + (size_t)seg * 128 * 896;
        bp = vb + (size_t)seg * 128;
        Out = vo + (long long)bz * S_ * 128; Nout = 128; cb0 = 0;
    }

    int tid  = threadIdx.x;
    int lane = tid & 31;
    int wid  = tid >> 5;
    int wm = (wid & 1) * 64;
    int wn = (wid >> 1) * 32;
    int gid = lane >> 2;
    int l4  = lane & 3;

    int lrow = tid >> 1;
    int lc   = (tid & 1) * 8;
    const float* gA0 = Ap + (long long)(m0 + lrow) * K + lc;
    const float* gB0 = W  + (long long)lrow * K + lc;

    uint32_t smem_u32;
    asm("{ .reg .u64 t; cvta.to.shared.u64 t, %1; cvt.u32.u64 %0, t; }"
        : "=r"(smem_u32) : "l"(sm));
    uint32_t sA0 = smem_u32 + (uint32_t)(lrow * PSTR + lc) * 4;
    uint32_t sB0 = sA0 + PSTAGES * 128 * PSTR * 4;

    float acc[4][4][4];
    #pragma unroll
    for (int mt = 0; mt < 4; mt++)
        #pragma unroll
        for (int nt = 0; nt < 4; nt++)
            #pragma unroll
            for (int j = 0; j < 4; j++) acc[mt][nt][j] = 0.f;

    gemm_mainloop(gA0, gB0, K / PBK, sA0, sB0, sm, wm, wn, gid, l4, acc);

    #pragma unroll
    for (int mt = 0; mt < 4; mt++) {
        #pragma unroll
        for (int nt = 0; nt < 4; nt++) {
            int mrow = m0 + wm + mt * 16 + gid;
            int cl   = wn + nt * 8 + 2 * l4;
            float b0 = bp[cl], b1 = bp[cl + 1];
            float2 v0 = make_float2(acc[mt][nt][0] + b0, acc[mt][nt][1] + b1);
            float2 v1 = make_float2(acc[mt][nt][2] + b0, acc[mt][nt][3] + b1);
            *(float2*)&Out[(long long)mrow * Nout + cb0 + cl]       = v0;
            *(float2*)&Out[(long long)(mrow + 8) * Nout + cb0 + cl] = v1;
        }
    }
}

// ---------------------------------------------------------------------------
// RoPE (in place on q and k). position id == s, theta = 1e6.
// ---------------------------------------------------------------------------
__global__ void rope_kernel(float* __restrict__ q, float* __restrict__ k)
{
    __shared__ float cs[32], sn[32];
    int t = blockIdx.x;
    int s = t % S_;
    if (threadIdx.x < 32) {
        int d = threadIdx.x;
        float inv = exp2f(-0.622664268228770f * (float)d);  // 1e6^(-d/32)
        float f = (float)s * inv;
        cs[d] = cosf(f);
        sn[d] = sinf(f);
    }
    __syncthreads();
    const int NQITEMS = NH_ * 32;
    const int NTOT = (NH_ + NKV_) * 32;
    for (int it = threadIdx.x; it < NTOT; it += blockDim.x) {
        float* base; int d;
        if (it < NQITEMS) { base = q + (size_t)t*NH_*HD_  + (it >> 5) * HD_; d = it & 31; }
        else { int j = it - NQITEMS; base = k + (size_t)t*NKV_*HD_ + (j >> 5) * HD_; d = j & 31; }
        float c = cs[d], sv = sn[d];
        float x1 = base[d], x2 = base[d + 32];
        base[d]      = x1 * c - x2 * sv;
        base[d + 32] = x2 * c + x1 * sv;
    }
}

// ---------------------------------------------------------------------------
// Tensor-core attention: flash online softmax with tf32 mma.
// Block = 64 q rows x 1 head; 4 warps, each owns 16 q rows.
// smem: qs[64][68] (Q*scale rna), ks[64][68] (K rna), vt[64][68] (V^T rna),
//       ps[4 warps][16][68] (P rna, per-warp private).
// FIX vs R15: tile loaders iterate j<8 (1024 float4 per 64x64 tile / 128 thr),
//             previously j<4 left rows 32..63 uninitialized (rel_err 0.87).
// Mask: allowed(q,k) = (k<S0) || (k<=q). kmax multiple of 64.
// ---------------------------------------------------------------------------
#define ASTR 68
#define ATT_SMEM_BYTES (4 * 64 * ASTR * 4)   // 69632

__global__ void __launch_bounds__(128)
attn_kernel(const float* __restrict__ q, const float* __restrict__ k,
            const float* __restrict__ v, float* __restrict__ o)
{
    extern __shared__ float asmem[];
    float* qs = asmem;                    // [64][ASTR]
    float* ks = asmem + 64 * ASTR;        // [64][ASTR]  (kv, hd)
    float* vt = asmem + 2 * 64 * ASTR;    // [64][ASTR]  (hd, kv)  V transposed
    float* ps = asmem + 3 * 64 * ASTR;    // 4 x [16][ASTR]

    int qt = blockIdx.x, h = blockIdx.y, b = blockIdx.z;
    int kvh = h / GQA_;
    int tid = threadIdx.x;
    int lane = tid & 31, w = tid >> 5;
    int gid = lane >> 2, l4 = lane & 3;
    float* psw = ps + w * 16 * ASTR;

    // Load Q tile (scaled + rna): 64x64 floats = 1024 float4 over 128 threads
    #pragma unroll
    for (int j = 0; j < 8; j++) {
        int idx = tid + 128 * j;          // 0..1023
        int r = idx >> 4;
        int c = (idx & 15) * 4;
        const float* qp = q + ((long long)b*S_ + qt*64 + r) * (NH_*HD_) + h*HD_ + c;
        float4 qv = *(const float4*)qp;
        float4 qr = make_float4(rna(qv.x*0.125f), rna(qv.y*0.125f),
                                rna(qv.z*0.125f), rna(qv.w*0.125f));
        *(float4*)&qs[r*ASTR + c] = qr;
    }
    __syncthreads();

    // Build Q fragments (persist whole kernel)
    uint32_t aq[8][4];
    #pragma unroll
    for (int ksp = 0; ksp < 8; ksp++) {
        aq[ksp][0] = __float_as_uint(qs[(w*16 + gid    )*ASTR + ksp*8 + l4    ]);
        aq[ksp][1] = __float_as_uint(qs[(w*16 + gid + 8)*ASTR + ksp*8 + l4    ]);
        aq[ksp][2] = __float_as_uint(qs[(w*16 + gid    )*ASTR + ksp*8 + l4 + 4]);
        aq[ksp][3] = __float_as_uint(qs[(w*16 + gid + 8)*ASTR + ksp*8 + l4 + 4]);
    }

    float oacc[8][4];
    #pragma unroll
    for (int nt = 0; nt < 8; nt++)
        #pragma unroll
        for (int j = 0; j < 4; j++) oacc[nt][j] = 0.f;
    float m0r = -1e30f, m1r = -1e30f, l0r = 0.f, l1r = 0.f;

    int r0g = qt*64 + w*16 + gid;        // global q row for c0,c1
    int r1g = r0g + 8;                   // global q row for c2,c3
    int qend = qt*64 + 63;
    int kmax = (qend < S0_) ? S0_ : (qend + 1);   // multiple of 64

    for (int k0 = 0; k0 < kmax; k0 += 64) {
        // Load K tile (rna) and V tile transposed (rna): 1024 float4 each
        #pragma unroll
        for (int j = 0; j < 8; j++) {
            int idx = tid + 128 * j;      // 0..1023
            int r = idx >> 4;
            int c = (idx & 15) * 4;
            const float* kp = k + ((long long)b*S_ + k0 + r) * (NKV_*HD_) + kvh*HD_ + c;
            float4 kv4 = *(const float4*)kp;
            float4 kr = make_float4(rna(kv4.x), rna(kv4.y), rna(kv4.z), rna(kv4.w));
            *(float4*)&ks[r*ASTR + c] = kr;
            const float* vp = v + ((long long)b*S_ + k0 + r) * (NKV_*HD_) + kvh*HD_ + c;
            float4 vv4 = *(const float4*)vp;
            vt[(c+0)*ASTR + r] = rna(vv4.x);
            vt[(c+1)*ASTR + r] = rna(vv4.y);
            vt[(c+2)*ASTR + r] = rna(vv4.z);
            vt[(c+3)*ASTR + r] = rna(vv4.w);
        }
        __syncthreads();

        // Scores: sacc[nt] = Q(16x64) @ K^T -> 16x64 per warp
        float sacc[8][4];
        #pragma unroll
        for (int nt = 0; nt < 8; nt++)
            #pragma unroll
            for (int j = 0; j < 4; j++) sacc[nt][j] = 0.f;

        #pragma unroll
        for (int ksp = 0; ksp < 8; ksp++) {
            uint32_t bf[8][2];
            #pragma unroll
            for (int nt = 0; nt < 8; nt++) {
                bf[nt][0] = __float_as_uint(ks[(nt*8 + gid)*ASTR + ksp*8 + l4    ]);
                bf[nt][1] = __float_as_uint(ks[(nt*8 + gid)*ASTR + ksp*8 + l4 + 4]);
            }
            #pragma unroll
            for (int nt = 0; nt < 8; nt++)
                mma_tf32(sacc[nt], aq[ksp], bf[nt]);
        }

        // Mask + row max
        float t0 = -1e30f, t1 = -1e30f;
        #pragma unroll
        for (int nt = 0; nt < 8; nt++) {
            int c0 = k0 + nt*8 + 2*l4;
            int c1 = c0 + 1;
            if (c0 > r0g && c0 >= S0_) sacc[nt][0] = -1e30f;
            if (c1 > r0g && c1 >= S0_) sacc[nt][1] = -1e30f;
            if (c0 > r1g && c0 >= S0_) sacc[nt][2] = -1e30f;
            if (c1 > r1g && c1 >= S0_) sacc[nt][3] = -1e30f;
            t0 = fmaxf(t0, fmaxf(sacc[nt][0], sacc[nt][1]));
            t1 = fmaxf(t1, fmaxf(sacc[nt][2], sacc[nt][3]));
        }
        t0 = fmaxf(t0, __shfl_xor_sync(0xffffffffu, t0, 1));
        t0 = fmaxf(t0, __shfl_xor_sync(0xffffffffu, t0, 2));
        t1 = fmaxf(t1, __shfl_xor_sync(0xffffffffu, t1, 1));
        t1 = fmaxf(t1, __shfl_xor_sync(0xffffffffu, t1, 2));

        float mn0 = fmaxf(m0r, t0), mn1 = fmaxf(m1r, t1);
        float cr0 = __expf(m0r - mn0), cr1 = __expf(m1r - mn1);
        l0r *= cr0; l1r *= cr1;
        #pragma unroll
        for (int nt = 0; nt < 8; nt++) {
            oacc[nt][0] *= cr0; oacc[nt][1] *= cr0;
            oacc[nt][2] *= cr1; oacc[nt][3] *= cr1;
        }

        // P = exp(S - m), accumulate l, store rna(P)
        float ls0 = 0.f, ls1 = 0.f;
        #pragma unroll
        for (int nt = 0; nt < 8; nt++) {
            float p0 = __expf(sacc[nt][0] - mn0);
            float p1 = __expf(sacc[nt][1] - mn0);
            float p2 = __expf(sacc[nt][2] - mn1);
            float p3 = __expf(sacc[nt][3] - mn1);
            ls0 += p0 + p1; ls1 += p2 + p3;
            *(float2*)&psw[(gid    )*ASTR + nt*8 + 2*l4] = make_float2(rna(p0), rna(p1));
            *(float2*)&psw[(gid + 8)*ASTR + nt*8 + 2*l4] = make_float2(rna(p2), rna(p3));
        }
        ls0 += __shfl_xor_sync(0xffffffffu, ls0, 1);
        ls0 += __shfl_xor_sync(0xffffffffu, ls0, 2);
        ls1 += __shfl_xor_sync(0xffffffffu, ls1, 1);
        ls1 += __shfl_xor_sync(0xffffffffu, ls1, 2);
        l0r += ls0; l1r += ls1;
        m0r = mn0; m1r = mn1;
        __syncwarp();

        // PV: oacc += P(16x64) @ V(64x64)
        #pragma unroll
        for (int ksp = 0; ksp < 8; ksp++) {
            uint32_t af[4];
            af[0] = __float_as_uint(psw[(gid    )*ASTR + ksp*8 + l4    ]);
            af[1] = __float_as_uint(psw[(gid + 8)*ASTR + ksp*8 + l4    ]);
            af[2] = __float_as_uint(psw[(gid    )*ASTR + ksp*8 + l4 + 4]);
            af[3] = __float_as_uint(psw[(gid + 8)*ASTR + ksp*8 + l4 + 4]);
            uint32_t bf[8][2];
            #pragma unroll
            for (int nt = 0; nt < 8; nt++) {
                bf[nt][0] = __float_as_uint(vt[(nt*8 + gid)*ASTR + ksp*8 + l4    ]);
                bf[nt][1] = __float_as_uint(vt[(nt*8 + gid)*ASTR + ksp*8 + l4 + 4]);
            }
            #pragma unroll
            for (int nt = 0; nt < 8; nt++)
                mma_tf32(oacc[nt], af, bf[nt]);
        }
        __syncthreads();   // before next tile overwrites ks/vt
    }

    float il0 = 1.f / l0r, il1 = 1.f / l1r;
    float* op0 = o + ((long long)b*S_ + r0g) * (NH_*HD_) + h*HD_;
    float* op1 = o + ((long long)b*S_ + r1g) * (NH_*HD_) + h*HD_;
    #pragma unroll
    for (int nt = 0; nt < 8; nt++) {
        int c = nt*8 + 2*l4;
        *(float2*)&op0[c] = make_float2(rna(oacc[nt][0]*il0), rna(oacc[nt][1]*il0));
        *(float2*)&op1[c] = make_float2(rna(oacc[nt][2]*il1), rna(oacc[nt][3]*il1));
    }
}

// ---------------------------------------------------------------------------
// Host launcher
// ---------------------------------------------------------------------------
extern "C" void kernel_launch(void* const* d_in, const int* in_sizes, int n_in,
                              void* d_out, int out_size)
{
    const float* x0 = (const float*)d_in[0];
    const float* x1 = (const float*)d_in[1];
    const float* x2 = (const float*)d_in[2];
    const float* qW = (const float*)d_in[3];
    const float* qb = (const float*)d_in[4];
    const float* kW = (const float*)d_in[5];
    const float* kb = (const float*)d_in[6];
    const float* vW = (const float*)d_in[7];
    const float* vb = (const float*)d_in[8];
    const float* oW = (const float*)d_in[9];
    const float* ln1 = (const float*)d_in[10];
    const float* ln2 = (const float*)d_in[11];
    const float* gW = (const float*)d_in[12];
    const float* uW = (const float*)d_in[13];
    const float* dW = (const float*)d_in[14];
    float* out = (float*)d_out;

    float *h, *q, *k, *v, *att, *res, *h2, *ga, *ua, *wtf;
    cudaGetSymbolAddress((void**)&h,   g_h);
    cudaGetSymbolAddress((void**)&q,   g_q);
    cudaGetSymbolAddress((void**)&k,   g_k);
    cudaGetSymbolAddress((void**)&v,   g_v);
    cudaGetSymbolAddress((void**)&att, g_att);
    cudaGetSymbolAddress((void**)&res, g_res);
    cudaGetSymbolAddress((void**)&h2,  g_h2);
    cudaGetSymbolAddress((void**)&ga,  g_ga);
    cudaGetSymbolAddress((void**)&ua,  g_ua);
    cudaGetSymbolAddress((void**)&wtf, g_wtf);

    cudaFuncSetAttribute(gemm_tc<0>, cudaFuncAttributeMaxDynamicSharedMemorySize, GEMM_SMEM_BYTES);
    cudaFuncSetAttribute(gemm_tc<1>, cudaFuncAttributeMaxDynamicSharedMemorySize, GEMM_SMEM_BYTES);
    cudaFuncSetAttribute(gemm_tc<2>, cudaFuncAttributeMaxDynamicSharedMemorySize, GEMM_SMEM_BYTES);
    cudaFuncSetAttribute(gemm_tc<3>, cudaFuncAttributeMaxDynamicSharedMemorySize, GEMM_SMEM_BYTES);
    cudaFuncSetAttribute(gemm_qkv,   cudaFuncAttributeMaxDynamicSharedMemorySize, GEMM_SMEM_BYTES);
    cudaFuncSetAttribute(attn_kernel, cudaFuncAttributeMaxDynamicSharedMemorySize, ATT_SMEM_BYTES);
    cudaFuncSetAttribute(gemm_tc<0>, cudaFuncAttributePreferredSharedMemoryCarveout, 100);
    cudaFuncSetAttribute(gemm_tc<1>, cudaFuncAttributePreferredSharedMemoryCarveout, 100);
    cudaFuncSetAttribute(gemm_tc<2>, cudaFuncAttributePreferredSharedMemoryCarveout, 100);
    cudaFuncSetAttribute(gemm_tc<3>, cudaFuncAttributePreferredSharedMemoryCarveout, 100);
    cudaFuncSetAttribute(gemm_qkv,   cudaFuncAttributePreferredSharedMemoryCarveout, 100);
    cudaFuncSetAttribute(attn_kernel, cudaFuncAttributePreferredSharedMemoryCarveout, 100);

    const int MT = S_ / 128;   // 16 m-tiles

    // 0. Weight prep
    wprep_kernel<<<2048, 256>>>(qW, kW, vW, oW, gW, uW, dW, wtf);

    // 1. RMSNorm(ln1) -> h (pre-rounded)
    rmsnorm1_kernel<<<B_ * S_, 256>>>(x0, x1, x2, ln1, h);

    // 2. Fused QKV projection
    gemm_qkv<<<dim3(9, MT, B_), 256, GEMM_SMEM_BYTES>>>(h, wtf, qb, kb, vb, q, k, v);

    // 3. RoPE (in place)
    rope_kernel<<<B_ * S_, 256>>>(q, k);

    // 4. Tensor-core attention (output pre-rounded)
    attn_kernel<<<dim3(S_ / 64, NH_, B_), 128, ATT_SMEM_BYTES>>>(q, k, v, att);

    // 5. O projection + segmented residual -> res
    gemm_tc<1><<<dim3(HID_/128, MT, B_), 256, GEMM_SMEM_BYTES>>>(
        att, (long long)S_*HID_, wtf + OFF_O, x0, x1, x2, 0,
        res, (long long)S_*HID_, HID_, HID_);

    // 6. RMSNorm(ln2) -> h2 (pre-rounded)
    rmsnorm2_kernel<<<B_ * S_, 256>>>(res, ln2, h2);

    // 7. MLP: gate GEMM -> ga, up GEMM with fused swiglu -> ua
    gemm_tc<0><<<dim3(INTER_/128, MT, B_), 256, GEMM_SMEM_BYTES>>>(
        h2, (long long)S_*HID_, wtf + OFF_G, nullptr, nullptr, nullptr, 0,
        ga, (long long)S_*INTER_, INTER_, HID_);
    gemm_tc<3><<<dim3(INTER_/128, MT, B_), 256, GEMM_SMEM_BYTES>>>(
        h2, (long long)S_*HID_, wtf + OFF_U, ga, nullptr, nullptr, (long long)S_*INTER_,
        ua, (long long)S_*INTER_, INTER_, HID_);

    // 8. Down projection + contiguous residual -> out
    gemm_tc<2><<<dim3(HID_/128, MT, B_), 256, GEMM_SMEM_BYTES>>>(
        ua, (long long)S_*INTER_, wtf + OFF_D, res, nullptr, nullptr, (long long)S_*HID_,
        out, (long long)S_*HID_, HID_, INTER_);
}